// round 12
// baseline (speedup 1.0000x reference)
#include <cuda_runtime.h>
#include <cuda_bf16.h>
#include <cuda_fp16.h>
#include <cstdint>

// Problem constants
#define Bn   4
#define Sn   4096
#define Dn   1024
#define Hn   8
#define Mn   32
#define Wn   16
#define NSn  128
#define GHn  128
#define TEMP 0.6f
#define SIGMA 0.12f
#define ALPHA 6.0f
#define HBS  (Hn * Bn * Sn)

#define SCALE_A 4096.0f
#define SCALE_B 32.0f
#define INV_SCALE (1.0f / (SCALE_A * SCALE_B))

// ---------------- scratch (device globals; no allocations allowed) ----------------
__device__ float g_pool_part[32 * Bn * Dn];
__device__ float g_weights[Hn * Bn * Mn];
__device__ float g_final[HBS];
__device__ float g_densP[2 * HBS];          // two NS-halves of raw density
__device__ float g_densSum[Hn * Bn];
__device__ __align__(16) __half g_Bh[(size_t)Dn * Dn];        // 2 MB: f16 Wo^T*32, [n][k]

// ---------------- PTX helpers (compute_100-safe) ----------------
__device__ __forceinline__ uint32_t smem_u32(const void* p) {
    uint32_t a;
    asm("{ .reg .u64 t; cvta.to.shared.u64 t, %1; cvt.u32.u64 %0, t; }" : "=r"(a) : "l"(p));
    return a;
}
#define CP16(dst, src) \
    asm volatile("cp.async.cg.shared.global [%0], [%1], 16;" :: "r"(dst), "l"(src))
#define CP_COMMIT() asm volatile("cp.async.commit_group;" ::: "memory")
#define CP_WAIT(n)  asm volatile("cp.async.wait_group %0;" :: "n"(n) : "memory")

#define LDSM4(r0, r1, r2, r3, addr)                                              \
    asm volatile("ldmatrix.sync.aligned.m8n8.x4.shared.b16 {%0,%1,%2,%3}, [%4];" \
                 : "=r"(r0), "=r"(r1), "=r"(r2), "=r"(r3) : "r"(addr))

// f16-in f16-accum MMA (32 C regs -> consumer fits 2-CTA register budget)
#define MMAF16(C, A, Bf)                                                        \
    asm volatile("mma.sync.aligned.m16n8k16.row.col.f16.f16.f16.f16 "           \
                 "{%0,%1},{%2,%3,%4,%5},{%6,%7},{%0,%1};\n"                     \
                 : "+r"(C[0]), "+r"(C[1])                                       \
                 : "r"(A[0]), "r"(A[1]), "r"(A[2]), "r"(A[3]),                  \
                   "r"(Bf[0]), "r"(Bf[1]))

// ---------------- 1) pooled partial sums over S ----------------
__global__ void pool_kernel(const float* __restrict__ x) {
    int d  = blockIdx.x * 256 + threadIdx.x;
    int sc = blockIdx.y;
    int b  = blockIdx.z;
    const float* xp = x + ((size_t)b * Sn + (size_t)sc * 128) * Dn + d;
    float a0 = 0.f, a1 = 0.f;
#pragma unroll 8
    for (int i = 0; i < 128; i += 2) {
        a0 += xp[(size_t)i * Dn];
        a1 += xp[(size_t)(i + 1) * Dn];
    }
    g_pool_part[(sc * Bn + b) * Dn + d] = a0 + a1;
}

// ---------------- 2) gating MLP -> softmax weights ----------------
__global__ void gate_kernel(const float* __restrict__ W1, const float* __restrict__ b1,
                            const float* __restrict__ W2, const float* __restrict__ b2) {
    int b = blockIdx.x, h = blockIdx.y, t = threadIdx.x;
    __shared__ float sp[Dn];
    __shared__ float sh[GHn];

    for (int i = t; i < Dn; i += 128) {
        float a = 0.f;
#pragma unroll
        for (int c = 0; c < 32; c++) a += g_pool_part[(c * Bn + b) * Dn + i];
        sp[i] = a * (1.0f / (float)Sn);
    }
    __syncthreads();
    {
        float acc = b1[h * GHn + t];
        const float* w1 = W1 + (size_t)h * Dn * GHn + t;
#pragma unroll 4
        for (int d = 0; d < Dn; d++) acc = fmaf(sp[d], w1[(size_t)d * GHn], acc);
        sh[t] = fmaxf(acc, 0.0f);
    }
    __syncthreads();
    if (t < Mn) {
        float l = b2[h * Mn + t];
        const float* w2 = W2 + h * GHn * Mn + t;
#pragma unroll
        for (int g = 0; g < GHn; g++) l = fmaf(sh[g], w2[g * Mn], l);
        l *= (1.0f / TEMP);
        float mx = l;
        for (int o = 16; o; o >>= 1) mx = fmaxf(mx, __shfl_xor_sync(0xffffffffu, mx, o));
        float e = __expf(l - mx);
        float sm = e;
        for (int o = 16; o; o >>= 1) sm += __shfl_xor_sync(0xffffffffu, sm, o);
        g_weights[(h * Bn + b) * Mn + t] = e / sm;
    }
    if (t == 0) g_densSum[h * Bn + b] = 0.f;
}

// ---------------- 3) waves -> gated final_grid ----------------
__global__ void wave_kernel(const float* __restrict__ freqs, const float* __restrict__ amps,
                            const float* __restrict__ phases) {
    int h = blockIdx.y, t = threadIdx.x;
    int s = blockIdx.x * 128 + t;
    __shared__ float sf0[Mn * Wn], sf1[Mn * Wn], sc[Mn * Wn], sa[Mn * Wn];
    __shared__ float sw[Bn * Mn];

    for (int i = t; i < Mn * Wn; i += 128) {
        sf0[i] = freqs[(h * Mn * Wn + i) * 2 + 0];
        sf1[i] = freqs[(h * Mn * Wn + i) * 2 + 1];
        sc[i] = (phases[h * Mn * Wn + i] - 1.5707963267948966f) * 0.15915494309189535f;
        sa[i] = amps[h * Mn * Wn + i];
    }
    sw[t] = g_weights[h * Bn * Mn + t];
    __syncthreads();

    float px = -1.0f + (2.0f / 63.0f) * (float)(s & 63);
    float py = -1.0f + (2.0f / 63.0f) * (float)(s >> 6);

    float fg0 = 0.f, fg1 = 0.f, fg2 = 0.f, fg3 = 0.f;
    for (int m = 0; m < Mn; m++) {
        float acc = 0.f;
#pragma unroll
        for (int w = 0; w < Wn; w++) {
            int i = m * Wn + w;
            float tt = fmaf(px, sf0[i], fmaf(py, sf1[i], sc[i]));
            float fr = tt - floorf(tt);
            acc = fmaf(sa[i], fmaf(-4.0f, fabsf(fr - 0.5f), 1.0f), acc);
        }
        fg0 = fmaf(sw[0 * Mn + m], acc, fg0);
        fg1 = fmaf(sw[1 * Mn + m], acc, fg1);
        fg2 = fmaf(sw[2 * Mn + m], acc, fg2);
        fg3 = fmaf(sw[3 * Mn + m], acc, fg3);
    }
    int base = h * Bn * Sn + s;
    g_final[base + 0 * Sn] = fg0;
    g_final[base + 1 * Sn] = fg1;
    g_final[base + 2 * Sn] = fg2;
    g_final[base + 3 * Sn] = fg3;
}

// ---------------- 4) MC density, float4 loads (NS split in 2) ----------------
__global__ void density_kernel(const float* __restrict__ noise) {
    int s = blockIdx.x * 1024 + threadIdx.x * 4;
    int b = blockIdx.y;
    int h = blockIdx.z >> 1, half = blockIdx.z & 1;
    int hb = h * Bn + b;
    float4 fg = *(const float4*)(g_final + hb * Sn + s);
    float zb0 = ALPHA * fg.x, zb1 = ALPHA * fg.y, zb2 = ALPHA * fg.z, zb3 = ALPHA * fg.w;
    const float* np_ = noise + ((size_t)hb * NSn + half * 64) * Sn + s;
    float a0 = 0.f, a1 = 0.f, a2 = 0.f, a3 = 0.f;
#pragma unroll 8
    for (int ns = 0; ns < 64; ns++) {
        float4 nz = *(const float4*)(np_ + (size_t)ns * Sn);
        float z0 = fmaf(ALPHA * SIGMA, nz.x, zb0);
        float z1 = fmaf(ALPHA * SIGMA, nz.y, zb1);
        float z2 = fmaf(ALPHA * SIGMA, nz.z, zb2);
        float z3 = fmaf(ALPHA * SIGMA, nz.w, zb3);
        a0 += __fdividef(1.0f, 1.0f + __expf(-z0));
        a1 += __fdividef(1.0f, 1.0f + __expf(-z1));
        a2 += __fdividef(1.0f, 1.0f + __expf(-z2));
        a3 += __fdividef(1.0f, 1.0f + __expf(-z3));
    }
    float4 v = make_float4(a0 * (1.0f / NSn), a1 * (1.0f / NSn),
                           a2 * (1.0f / NSn), a3 * (1.0f / NSn));
    *(float4*)(g_densP + half * HBS + hb * Sn + s) = v;

    float r = v.x + v.y + v.z + v.w;
    for (int o = 16; o; o >>= 1) r += __shfl_xor_sync(0xffffffffu, r, o);
    __shared__ float sred[8];
    if ((threadIdx.x & 31) == 0) sred[threadIdx.x >> 5] = r;
    __syncthreads();
    if (threadIdx.x < 8) {
        float rr = sred[threadIdx.x];
        for (int o = 4; o; o >>= 1) rr += __shfl_xor_sync(0xffu, rr, o);
        if (threadIdx.x == 0) atomicAdd(&g_densSum[hb], rr);
    }
}

// ---------------- 5b) prep B: Wo^T * 32 -> f16 [n][k] ----------------
__global__ void prepB_kernel(const float* __restrict__ Wo) {
    __shared__ float tile[32][33];
    int k0 = blockIdx.x * 32, n0 = blockIdx.y * 32;
    int c = threadIdx.x & 31, r0 = threadIdx.x >> 5;
#pragma unroll
    for (int i = 0; i < 4; i++)
        tile[r0 + 8 * i][c] = Wo[(size_t)(k0 + r0 + 8 * i) * Dn + n0 + c];
    __syncthreads();
    int c2 = (threadIdx.x & 15) * 2, r = threadIdx.x >> 4;
#pragma unroll
    for (int i = 0; i < 2; i++) {
        int rr = r + 16 * i;
        __half2 p = __floats2half2_rn(tile[c2][rr] * SCALE_B, tile[c2 + 1][rr] * SCALE_B);
        *(__half2*)(g_Bh + (size_t)(n0 + rr) * Dn + k0 + c2) = p;
    }
}

// ---------------- 5c) warp-specialized GEMM: out = (dens*x) @ Wo + x + bo -------
// 384 threads: warps 0-7 = consumers (pure LDSM+MMA, f16 accum), warps 8-11 =
// producers (A: LDG fp32 x -> scale -> cvt f16 -> STS; B: cp.async + exact
// one-commit-per-iteration accounting). CTA 128x128, BK=64, 3-stage ring, one
// __syncthreads per k-tile as the producer->consumer handoff. 2 CTAs/SM.
#define NSTG 3
#define NKT  16
#define STAGE_BYTES 32768        // A 16KB + B 16KB
#define SSC_OFF (NSTG * STAGE_BYTES)
#define GEMM_SMEM   (SSC_OFF + 4096)

__global__ __launch_bounds__(384, 2) void gemm_kernel(const float* __restrict__ x,
                                                      const float* __restrict__ bo,
                                                      float* __restrict__ out) {
    extern __shared__ __align__(16) uint8_t dsm[];
    const uint32_t tiles = smem_u32(dsm);
    float* ssc = (float*)(dsm + SSC_OFF);         // [h][row] scale * SCALE_A

    const int tid = threadIdx.x;
    const int nb = blockIdx.x, mb = blockIdx.y;
    const int bidx = mb >> 5;
    const int s0 = (mb & 31) * 128;

    // per-(head,row) normalized density scale table (all threads help)
    for (int i = tid; i < Hn * 128; i += 384) {
        int h = i >> 7, r = i & 127;
        int hb = h * Bn + bidx;
        ssc[i] = (g_densP[hb * Sn + s0 + r] + g_densP[HBS + hb * Sn + s0 + r]) /
                 (g_densSum[hb] + 1e-8f) * SCALE_A;
    }

    if (tid >= 256) {
        // ================= PRODUCER (warps 8-11, 128 threads) =================
        const int t2 = tid - 256;
        const int prow = t2 >> 3;          // base row, +16 per pass (8 passes)
        const int pch  = t2 & 7;           // 16B chunk within 128B row
        const __half* Bgp = g_Bh + (size_t)(nb * 128 + prow) * Dn + pch * 8;
        const float*  Axp = x + (size_t)(mb * 128 + prow) * Dn + pch * 8;

        auto issueB = [&](int kt, int st) {
            uint32_t dB = tiles + st * STAGE_BYTES + 16384;
            int k0 = kt * 64;
#pragma unroll
            for (int p = 0; p < 8; p++) {
                int row = prow + p * 16;
                CP16(dB + row * 128 + ((pch ^ (row & 7)) << 4),
                     Bgp + (size_t)p * 16 * Dn + k0);
            }
            CP_COMMIT();
        };
        auto produceA = [&](int kt, int st) {
            int k0 = kt * 64;
            int h = kt >> 1;
#pragma unroll
            for (int p = 0; p < 8; p++) {
                int row = prow + p * 16;
                float sc = ssc[h * 128 + row];
                float4 v0 = *(const float4*)(Axp + (size_t)p * 16 * Dn + k0);
                float4 v1 = *(const float4*)(Axp + (size_t)p * 16 * Dn + k0 + 4);
                __half2 q0 = __floats2half2_rn(v0.x * sc, v0.y * sc);
                __half2 q1 = __floats2half2_rn(v0.z * sc, v0.w * sc);
                __half2 q2 = __floats2half2_rn(v1.x * sc, v1.y * sc);
                __half2 q3 = __floats2half2_rn(v1.z * sc, v1.w * sc);
                uint4 o;
                o.x = *(uint32_t*)&q0; o.y = *(uint32_t*)&q1;
                o.z = *(uint32_t*)&q2; o.w = *(uint32_t*)&q3;
                *(uint4*)(dsm + st * STAGE_BYTES + row * 128 +
                          ((pch ^ (row & 7)) << 4)) = o;
            }
        };

        issueB(0, 0);
        issueB(1, 1);
        __syncthreads();                   // ssc table ready (barrier #0)
        produceA(0, 0);
        CP_WAIT(1);                        // B(0) complete

        int st = 0;
        for (int kt = 0; kt < NKT; kt++) {
            __syncthreads();               // publish stage st to consumers
            if (kt + 2 < NKT) {
                int s2 = st + 2; if (s2 >= NSTG) s2 -= NSTG;
                issueB(kt + 2, s2);
            } else {
                CP_COMMIT();               // keep wait-depth arithmetic exact
            }
            CP_WAIT(1);                    // B(kt+1) complete
            if (kt + 1 < NKT) {
                int s1 = st + 1; if (s1 >= NSTG) s1 -= NSTG;
                produceA(kt + 1, s1);
            }
            if (++st == NSTG) st = 0;
        }
        // producers exit; no further barriers on either path
    } else {
        // ================= CONSUMER (warps 0-7, pure MMA) =====================
        const int warpId = tid >> 5, lane = tid & 31;
        const int wm = warpId & 1, wn = warpId >> 1;
        const int g = lane >> 2, t4 = lane & 3;

        int amRB[4], amRK[4];
#pragma unroll
        for (int mt = 0; mt < 4; mt++) {
            int amRow = wm * 64 + mt * 16 + (lane & 15);
            amRB[mt] = amRow * 128;
            amRK[mt] = amRow & 7;
        }
        const int ahi = lane >> 4;
        int bnRB[2], bnRK[2];
        const int nidx = (lane & 7) | ((lane >> 1) & 8);
#pragma unroll
        for (int nt2 = 0; nt2 < 2; nt2++) {
            int bnRow = wn * 32 + nt2 * 16 + nidx;
            bnRB[nt2] = bnRow * 128;
            bnRK[nt2] = bnRow & 7;
        }
        const int bhi = (lane >> 3) & 1;

        uint32_t c_[4][4][2] = {};

        __syncthreads();                   // matches producer barrier #0

        int st = 0;
        for (int kt = 0; kt < NKT; kt++) {
            __syncthreads();               // stage st ready (A STS + B awaited)

            uint32_t aB = tiles + st * STAGE_BYTES;
            uint32_t bB = aB + 16384;
#pragma unroll
            for (int ks = 0; ks < 4; ks++) {
                uint32_t af[4][4], bf[2][4];
                const int cca = 2 * ks + ahi;
                const int ccb = 2 * ks + bhi;
#pragma unroll
                for (int mt = 0; mt < 4; mt++)
                    LDSM4(af[mt][0], af[mt][1], af[mt][2], af[mt][3],
                          aB + amRB[mt] + ((cca ^ amRK[mt]) << 4));
#pragma unroll
                for (int nt2 = 0; nt2 < 2; nt2++)
                    LDSM4(bf[nt2][0], bf[nt2][1], bf[nt2][2], bf[nt2][3],
                          bB + bnRB[nt2] + ((ccb ^ bnRK[nt2]) << 4));
#pragma unroll
                for (int mt = 0; mt < 4; mt++)
#pragma unroll
                    for (int nt = 0; nt < 4; nt++) {
                        uint32_t bb[2] = {bf[nt >> 1][(nt & 1) * 2],
                                          bf[nt >> 1][(nt & 1) * 2 + 1]};
                        MMAF16(c_[mt][nt], af[mt], bb);
                    }
            }
            if (++st == NSTG) st = 0;
        }

        // epilogue: unpack f16 accum, rescale, + x + bo
#pragma unroll
        for (int mt = 0; mt < 4; mt++) {
            int r0 = mb * 128 + wm * 64 + mt * 16 + g;
#pragma unroll
            for (int nt = 0; nt < 4; nt++) {
                int cc = nb * 128 + wn * 32 + nt * 8 + 2 * t4;
                float2 bo2 = *(const float2*)(bo + cc);
                float2 x0 = *(const float2*)(x + (size_t)r0 * Dn + cc);
                float2 x1 = *(const float2*)(x + (size_t)(r0 + 8) * Dn + cc);
                float2 v0 = __half22float2(*(__half2*)&c_[mt][nt][0]);
                float2 v1 = __half22float2(*(__half2*)&c_[mt][nt][1]);
                float2 o0 = make_float2(fmaf(v0.x, INV_SCALE, x0.x + bo2.x),
                                        fmaf(v0.y, INV_SCALE, x0.y + bo2.y));
                float2 o1 = make_float2(fmaf(v1.x, INV_SCALE, x1.x + bo2.x),
                                        fmaf(v1.y, INV_SCALE, x1.y + bo2.y));
                *(float2*)(out + (size_t)r0 * Dn + cc) = o0;
                *(float2*)(out + (size_t)(r0 + 8) * Dn + cc) = o1;
            }
        }
    }
}

// ---------------- launcher ----------------
extern "C" void kernel_launch(void* const* d_in, const int* in_sizes, int n_in,
                              void* d_out, int out_size) {
    const float* x      = (const float*)d_in[0];
    const float* noise  = (const float*)d_in[1];
    const float* W1     = (const float*)d_in[2];
    const float* b1     = (const float*)d_in[3];
    const float* W2     = (const float*)d_in[4];
    const float* b2     = (const float*)d_in[5];
    const float* freqs  = (const float*)d_in[6];
    const float* amps   = (const float*)d_in[7];
    const float* phases = (const float*)d_in[8];
    const float* Wo     = (const float*)d_in[9];
    const float* bo     = (const float*)d_in[10];
    float* out          = (float*)d_out;

    // idempotent, capture-safe; called unconditionally
    cudaFuncSetAttribute(gemm_kernel, cudaFuncAttributeMaxDynamicSharedMemorySize,
                         GEMM_SMEM);

    pool_kernel<<<dim3(Dn / 256, 32, Bn), 256>>>(x);
    gate_kernel<<<dim3(Bn, Hn), 128>>>(W1, b1, W2, b2);
    wave_kernel<<<dim3(Sn / 128, Hn), 128>>>(freqs, amps, phases);
    prepB_kernel<<<dim3(32, 32), 256>>>(Wo);
    density_kernel<<<dim3(Sn / 1024, Bn, Hn * 2), 256>>>(noise);
    gemm_kernel<<<dim3(Dn / 128, (Bn * Sn) / 128), 384, GEMM_SMEM>>>(x, bo, out);
}

// round 16
// speedup vs baseline: 1.1064x; 1.1064x over previous
#include <cuda_runtime.h>
#include <cuda_bf16.h>
#include <cstdint>

// Problem constants
#define Bn   4
#define Sn   4096
#define Dn   1024
#define Hn   8
#define Mn   32
#define Wn   16
#define NSn  128
#define GHn  128
#define TEMP 0.6f
#define SIGMA 0.12f
#define ALPHA 6.0f
#define HBS  (Hn * Bn * Sn)

// ---------------- scratch (device globals; no allocations allowed) ----------------
__device__ float g_pool_part[32 * Bn * Dn];
__device__ float g_weights[Hn * Bn * Mn];
__device__ float g_final[HBS];
__device__ float g_densP[2 * HBS];          // two NS-halves of raw density
__device__ float g_densSum[Hn * Bn];
__device__ __align__(16) __nv_bfloat16 g_Abf[(size_t)Bn * Sn * Dn];  // 32 MB scaled x, bf16
__device__ __align__(16) __nv_bfloat16 g_Bt[(size_t)Dn * Dn];        // 2 MB Wo^T [n][k] bf16

// ---------------- PTX helpers (compute_100-safe) ----------------
__device__ __forceinline__ uint32_t smem_u32(const void* p) {
    uint32_t a;
    asm("{ .reg .u64 t; cvta.to.shared.u64 t, %1; cvt.u32.u64 %0, t; }" : "=r"(a) : "l"(p));
    return a;
}
#define CP16(dst, src) \
    asm volatile("cp.async.cg.shared.global [%0], [%1], 16;" :: "r"(dst), "l"(src))
#define CP_COMMIT() asm volatile("cp.async.commit_group;" ::: "memory")
#define CP_WAIT(n)  asm volatile("cp.async.wait_group %0;" :: "n"(n) : "memory")

#define LDSM4(r0, r1, r2, r3, addr)                                              \
    asm volatile("ldmatrix.sync.aligned.m8n8.x4.shared.b16 {%0,%1,%2,%3}, [%4];" \
                 : "=r"(r0), "=r"(r1), "=r"(r2), "=r"(r3) : "r"(addr))

#define MMA16816(C, A, Bf)                                                      \
    asm volatile("mma.sync.aligned.m16n8k16.row.col.f32.bf16.bf16.f32 "         \
                 "{%0,%1,%2,%3},{%4,%5,%6,%7},{%8,%9},{%0,%1,%2,%3};\n"         \
                 : "+f"(C[0]), "+f"(C[1]), "+f"(C[2]), "+f"(C[3])               \
                 : "r"(A[0]), "r"(A[1]), "r"(A[2]), "r"(A[3]),                  \
                   "r"(Bf[0]), "r"(Bf[1]))

// ---------------- 1) pooled partial sums over S ----------------
__global__ void pool_kernel(const float* __restrict__ x) {
    int d  = blockIdx.x * 256 + threadIdx.x;
    int sc = blockIdx.y;
    int b  = blockIdx.z;
    const float* xp = x + ((size_t)b * Sn + (size_t)sc * 128) * Dn + d;
    float a0 = 0.f, a1 = 0.f;
#pragma unroll 8
    for (int i = 0; i < 128; i += 2) {
        a0 += xp[(size_t)i * Dn];
        a1 += xp[(size_t)(i + 1) * Dn];
    }
    g_pool_part[(sc * Bn + b) * Dn + d] = a0 + a1;
}

// ---------------- 2) gating MLP -> softmax weights ----------------
__global__ void gate_kernel(const float* __restrict__ W1, const float* __restrict__ b1,
                            const float* __restrict__ W2, const float* __restrict__ b2) {
    int b = blockIdx.x, h = blockIdx.y, t = threadIdx.x;
    __shared__ float sp[Dn];
    __shared__ float sh[GHn];

    for (int i = t; i < Dn; i += 128) {
        float a = 0.f;
#pragma unroll
        for (int c = 0; c < 32; c++) a += g_pool_part[(c * Bn + b) * Dn + i];
        sp[i] = a * (1.0f / (float)Sn);
    }
    __syncthreads();
    {
        float acc = b1[h * GHn + t];
        const float* w1 = W1 + (size_t)h * Dn * GHn + t;
#pragma unroll 4
        for (int d = 0; d < Dn; d++) acc = fmaf(sp[d], w1[(size_t)d * GHn], acc);
        sh[t] = fmaxf(acc, 0.0f);
    }
    __syncthreads();
    if (t < Mn) {
        float l = b2[h * Mn + t];
        const float* w2 = W2 + h * GHn * Mn + t;
#pragma unroll
        for (int g = 0; g < GHn; g++) l = fmaf(sh[g], w2[g * Mn], l);
        l *= (1.0f / TEMP);
        float mx = l;
        for (int o = 16; o; o >>= 1) mx = fmaxf(mx, __shfl_xor_sync(0xffffffffu, mx, o));
        float e = __expf(l - mx);
        float sm = e;
        for (int o = 16; o; o >>= 1) sm += __shfl_xor_sync(0xffffffffu, sm, o);
        g_weights[(h * Bn + b) * Mn + t] = e / sm;
    }
    if (t == 0) g_densSum[h * Bn + b] = 0.f;
}

// ---------------- 3) waves -> gated final_grid ----------------
__global__ void wave_kernel(const float* __restrict__ freqs, const float* __restrict__ amps,
                            const float* __restrict__ phases) {
    int h = blockIdx.y, t = threadIdx.x;
    int s = blockIdx.x * 128 + t;
    __shared__ float sf0[Mn * Wn], sf1[Mn * Wn], sc[Mn * Wn], sa[Mn * Wn];
    __shared__ float sw[Bn * Mn];

    for (int i = t; i < Mn * Wn; i += 128) {
        sf0[i] = freqs[(h * Mn * Wn + i) * 2 + 0];
        sf1[i] = freqs[(h * Mn * Wn + i) * 2 + 1];
        sc[i] = (phases[h * Mn * Wn + i] - 1.5707963267948966f) * 0.15915494309189535f;
        sa[i] = amps[h * Mn * Wn + i];
    }
    sw[t] = g_weights[h * Bn * Mn + t];
    __syncthreads();

    float px = -1.0f + (2.0f / 63.0f) * (float)(s & 63);
    float py = -1.0f + (2.0f / 63.0f) * (float)(s >> 6);

    float fg0 = 0.f, fg1 = 0.f, fg2 = 0.f, fg3 = 0.f;
    for (int m = 0; m < Mn; m++) {
        float acc = 0.f;
#pragma unroll
        for (int w = 0; w < Wn; w++) {
            int i = m * Wn + w;
            float tt = fmaf(px, sf0[i], fmaf(py, sf1[i], sc[i]));
            float fr = tt - floorf(tt);
            acc = fmaf(sa[i], fmaf(-4.0f, fabsf(fr - 0.5f), 1.0f), acc);
        }
        fg0 = fmaf(sw[0 * Mn + m], acc, fg0);
        fg1 = fmaf(sw[1 * Mn + m], acc, fg1);
        fg2 = fmaf(sw[2 * Mn + m], acc, fg2);
        fg3 = fmaf(sw[3 * Mn + m], acc, fg3);
    }
    int base = h * Bn * Sn + s;
    g_final[base + 0 * Sn] = fg0;
    g_final[base + 1 * Sn] = fg1;
    g_final[base + 2 * Sn] = fg2;
    g_final[base + 3 * Sn] = fg3;
}

// ---------------- 4) MC density, float4 loads (NS split in 2) ----------------
// grid (Sn/1024, Bn, Hn*2), block 256; each thread: 4 consecutive s
__global__ void density_kernel(const float* __restrict__ noise) {
    int s = blockIdx.x * 1024 + threadIdx.x * 4;
    int b = blockIdx.y;
    int h = blockIdx.z >> 1, half = blockIdx.z & 1;
    int hb = h * Bn + b;
    float4 fg = *(const float4*)(g_final + hb * Sn + s);
    float zb0 = ALPHA * fg.x, zb1 = ALPHA * fg.y, zb2 = ALPHA * fg.z, zb3 = ALPHA * fg.w;
    const float* np_ = noise + ((size_t)hb * NSn + half * 64) * Sn + s;
    float a0 = 0.f, a1 = 0.f, a2 = 0.f, a3 = 0.f;
#pragma unroll 8
    for (int ns = 0; ns < 64; ns++) {
        float4 nz = *(const float4*)(np_ + (size_t)ns * Sn);
        float z0 = fmaf(ALPHA * SIGMA, nz.x, zb0);
        float z1 = fmaf(ALPHA * SIGMA, nz.y, zb1);
        float z2 = fmaf(ALPHA * SIGMA, nz.z, zb2);
        float z3 = fmaf(ALPHA * SIGMA, nz.w, zb3);
        a0 += __fdividef(1.0f, 1.0f + __expf(-z0));
        a1 += __fdividef(1.0f, 1.0f + __expf(-z1));
        a2 += __fdividef(1.0f, 1.0f + __expf(-z2));
        a3 += __fdividef(1.0f, 1.0f + __expf(-z3));
    }
    float4 v = make_float4(a0 * (1.0f / NSn), a1 * (1.0f / NSn),
                           a2 * (1.0f / NSn), a3 * (1.0f / NSn));
    *(float4*)(g_densP + half * HBS + hb * Sn + s) = v;

    float r = v.x + v.y + v.z + v.w;
    for (int o = 16; o; o >>= 1) r += __shfl_xor_sync(0xffffffffu, r, o);
    __shared__ float sred[8];
    if ((threadIdx.x & 31) == 0) sred[threadIdx.x >> 5] = r;
    __syncthreads();
    if (threadIdx.x < 8) {
        float rr = sred[threadIdx.x];
        for (int o = 4; o; o >>= 1) rr += __shfl_xor_sync(0xffu, rr, o);
        if (threadIdx.x == 0) atomicAdd(&g_densSum[hb], rr);
    }
}

// ---------------- 5a) prep A: density-scaled x -> bf16 row-major ----------------
// grid 8192, block 256 (2 rows per block, 8 cols per thread)
__global__ void prepA_kernel(const float* __restrict__ x) {
    int t = threadIdx.x;
    int R = blockIdx.x * 2 + (t >> 7);
    int c0 = (t & 127) * 8;
    int b = R >> 12, s = R & 4095, h = c0 >> 7;
    int hb = h * Bn + b;
    float sc = (g_densP[hb * Sn + s] + g_densP[HBS + hb * Sn + s]) /
               (g_densSum[hb] + 1e-8f);

    const float4* src = (const float4*)(x + (size_t)R * Dn + c0);
    float4 v0 = src[0], v1 = src[1];
    __nv_bfloat162 p0 = __floats2bfloat162_rn(v0.x * sc, v0.y * sc);
    __nv_bfloat162 p1 = __floats2bfloat162_rn(v0.z * sc, v0.w * sc);
    __nv_bfloat162 p2 = __floats2bfloat162_rn(v1.x * sc, v1.y * sc);
    __nv_bfloat162 p3 = __floats2bfloat162_rn(v1.z * sc, v1.w * sc);
    uint4 o;
    o.x = *(uint32_t*)&p0; o.y = *(uint32_t*)&p1;
    o.z = *(uint32_t*)&p2; o.w = *(uint32_t*)&p3;
    *(uint4*)(g_Abf + (size_t)R * Dn + c0) = o;
}

// ---------------- 5b) prep B: transpose Wo -> bf16 [n][k] ----------------
// grid (32, 32), block 256
__global__ void prepB_kernel(const float* __restrict__ Wo) {
    __shared__ float tile[32][33];
    int k0 = blockIdx.x * 32, n0 = blockIdx.y * 32;
    int c = threadIdx.x & 31, r0 = threadIdx.x >> 5;
#pragma unroll
    for (int i = 0; i < 4; i++)
        tile[r0 + 8 * i][c] = Wo[(size_t)(k0 + r0 + 8 * i) * Dn + n0 + c];
    __syncthreads();
    int c2 = (threadIdx.x & 15) * 2, r = threadIdx.x >> 4;
#pragma unroll
    for (int i = 0; i < 2; i++) {
        int rr = r + 16 * i;
        __nv_bfloat162 p = __floats2bfloat162_rn(tile[c2][rr], tile[c2 + 1][rr]);
        *(__nv_bfloat162*)(g_Bt + (size_t)(n0 + rr) * Dn + k0 + c2) = p;
    }
}

// ---------------- 5c) HMMA GEMM: out = (dens*x) @ Wo + x + bo ----------------
// The 298.3us-proven kernel: CTA 128x128, BK=64, 3-stage cp.async (96KB -> 2
// CTAs/SM), 256 thr, 8 warps (2m x 4n), warp 64x32, m16n8k16 bf16 f32-accum,
// ldmatrix.x4, xor swizzle, ONE barrier per k-tile. Tail fix: exactly one
// commit group per iteration (empty at tail) so CP_WAIT(1) is always exact.
#define NSTG 3
#define NKT  16
#define STAGE_BYTES 32768        // A 16KB + B 16KB
#define GEMM_SMEM   (NSTG * STAGE_BYTES)

__global__ __launch_bounds__(256, 2) void gemm_kernel(const float* __restrict__ x,
                                                      const float* __restrict__ bo,
                                                      float* __restrict__ out) {
    extern __shared__ __align__(16) uint8_t dsm[];
    const uint32_t tiles = smem_u32(dsm);

    const int tid = threadIdx.x;
    const int nb = blockIdx.x, mb = blockIdx.y;
    const int warpId = tid >> 5, lane = tid & 31;
    const int wm = warpId & 1, wn = warpId >> 1;
    const int g = lane >> 2, t4 = lane & 3;

    // loader mapping: 4 rows-of-32 per thread, 16B chunk per row
    const int arow = tid >> 3, acol = tid & 7;
    const __nv_bfloat16* Agp = g_Abf + (size_t)(mb * 128 + arow) * Dn + acol * 8;
    const __nv_bfloat16* Bgp = g_Bt + (size_t)(nb * 128 + arow) * Dn + acol * 8;

    auto issue = [&](int kt, int st) {
        uint32_t dA = tiles + st * STAGE_BYTES;
        uint32_t dB = dA + 16384;
        int k0 = kt * 64;
#pragma unroll
        for (int p = 0; p < 4; p++) {
            int row = arow + p * 32;
            uint32_t off = row * 128 + ((acol ^ (row & 7)) << 4);
            CP16(dA + off, Agp + (size_t)p * 32 * Dn + k0);
            CP16(dB + off, Bgp + (size_t)p * 32 * Dn + k0);
        }
        CP_COMMIT();
    };

    // ldmatrix per-lane address components (fixed across k)
    int amRB[4], amRK[4];
#pragma unroll
    for (int mt = 0; mt < 4; mt++) {
        int amRow = wm * 64 + mt * 16 + (lane & 15);
        amRB[mt] = amRow * 128;
        amRK[mt] = amRow & 7;
    }
    const int ahi = lane >> 4;                           // A k-chunk high bit
    int bnRB[2], bnRK[2];
    const int nidx = (lane & 7) | ((lane >> 1) & 8);
#pragma unroll
    for (int nt2 = 0; nt2 < 2; nt2++) {
        int bnRow = wn * 32 + nt2 * 16 + nidx;
        bnRB[nt2] = bnRow * 128;
        bnRK[nt2] = bnRow & 7;
    }
    const int bhi = (lane >> 3) & 1;                     // B k-chunk high bit

    float c_[4][4][4] = {};

    issue(0, 0);
    issue(1, 1);

    int st = 0;
    for (int kt = 0; kt < NKT; kt++) {
        CP_WAIT(1);
        __syncthreads();

        // exactly one commit per iteration (prefetch or empty) keeps wait depth exact
        if (kt + 2 < NKT) {
            int stNext = st + 2;
            if (stNext >= NSTG) stNext -= NSTG;
            issue(kt + 2, stNext);
        } else {
            CP_COMMIT();
        }

        uint32_t aB = tiles + st * STAGE_BYTES;
        uint32_t bB = aB + 16384;

#pragma unroll
        for (int ks = 0; ks < 4; ks++) {
            uint32_t af[4][4], bf[2][4];
            const int cca = 2 * ks + ahi;
            const int ccb = 2 * ks + bhi;
#pragma unroll
            for (int mt = 0; mt < 4; mt++)
                LDSM4(af[mt][0], af[mt][1], af[mt][2], af[mt][3],
                      aB + amRB[mt] + ((cca ^ amRK[mt]) << 4));
#pragma unroll
            for (int nt2 = 0; nt2 < 2; nt2++)
                LDSM4(bf[nt2][0], bf[nt2][1], bf[nt2][2], bf[nt2][3],
                      bB + bnRB[nt2] + ((ccb ^ bnRK[nt2]) << 4));
#pragma unroll
            for (int mt = 0; mt < 4; mt++)
#pragma unroll
                for (int nt = 0; nt < 4; nt++) {
                    uint32_t bb[2] = {bf[nt >> 1][(nt & 1) * 2],
                                      bf[nt >> 1][(nt & 1) * 2 + 1]};
                    MMA16816(c_[mt][nt], af[mt], bb);
                }
        }

        if (++st == NSTG) st = 0;
    }

    // epilogue: + x + bo
#pragma unroll
    for (int mt = 0; mt < 4; mt++) {
        int r0 = mb * 128 + wm * 64 + mt * 16 + g;
#pragma unroll
        for (int nt = 0; nt < 4; nt++) {
            int cc = nb * 128 + wn * 32 + nt * 8 + 2 * t4;
            float2 bo2 = *(const float2*)(bo + cc);
            float2 x0 = *(const float2*)(x + (size_t)r0 * Dn + cc);
            float2 x1 = *(const float2*)(x + (size_t)(r0 + 8) * Dn + cc);
            float2 o0 = make_float2(c_[mt][nt][0] + x0.x + bo2.x,
                                    c_[mt][nt][1] + x0.y + bo2.y);
            float2 o1 = make_float2(c_[mt][nt][2] + x1.x + bo2.x,
                                    c_[mt][nt][3] + x1.y + bo2.y);
            *(float2*)(out + (size_t)r0 * Dn + cc) = o0;
            *(float2*)(out + (size_t)(r0 + 8) * Dn + cc) = o1;
        }
    }
}

// ---------------- launcher ----------------
extern "C" void kernel_launch(void* const* d_in, const int* in_sizes, int n_in,
                              void* d_out, int out_size) {
    const float* x      = (const float*)d_in[0];
    const float* noise  = (const float*)d_in[1];
    const float* W1     = (const float*)d_in[2];
    const float* b1     = (const float*)d_in[3];
    const float* W2     = (const float*)d_in[4];
    const float* b2     = (const float*)d_in[5];
    const float* freqs  = (const float*)d_in[6];
    const float* amps   = (const float*)d_in[7];
    const float* phases = (const float*)d_in[8];
    const float* Wo     = (const float*)d_in[9];
    const float* bo     = (const float*)d_in[10];
    float* out          = (float*)d_out;

    // idempotent, capture-safe; called unconditionally (no static guards)
    cudaFuncSetAttribute(gemm_kernel, cudaFuncAttributeMaxDynamicSharedMemorySize,
                         GEMM_SMEM);

    pool_kernel<<<dim3(Dn / 256, 32, Bn), 256>>>(x);
    gate_kernel<<<dim3(Bn, Hn), 128>>>(W1, b1, W2, b2);
    wave_kernel<<<dim3(Sn / 128, Hn), 128>>>(freqs, amps, phases);
    prepB_kernel<<<dim3(32, 32), 256>>>(Wo);
    density_kernel<<<dim3(Sn / 1024, Bn, Hn * 2), 256>>>(noise);
    prepA_kernel<<<8192, 256>>>(x);
    gemm_kernel<<<dim3(Dn / 128, (Bn * Sn) / 128), 256, GEMM_SMEM>>>(x, bo, out);
}